// round 14
// baseline (speedup 1.0000x reference)
#include <cuda_runtime.h>
#include <cuda_fp16.h>
#include <cstdint>

#define BB 32
#define SS 2048
#define DD 512
#define UU 512
#define ROWS (BB*SS)          // 65536
#define NTILES 4
#define PITCH 144             // 64 halfs (128B) + 16B pad; conflict-free ldsm

// dynamic smem: 3 stages of (A 256x144 | B 128x144)  [R8 config — measured best]
#define STG_BYTES 55296
#define SM_HP  165888
#define SM_VW  166400
#define SM_RED 166912
#define SM_SCORE_BYTES 171008

// prep kernel dispatch
#define PREP_A2H_BLOCKS   8192
#define PREP_HPROJ_BLOCKS 32
#define PREP_W1_BLOCKS    256
#define PREP_BLOCKS (PREP_A2H_BLOCKS + PREP_HPROJ_BLOCKS + PREP_W1_BLOCKS)

// ---------------- scratch (no allocation allowed) ----------------
__device__ float g_hp[BB*UU];
__device__ float g_partial[NTILES][ROWS];
__device__ __half g_Bh[UU*DD];            // W1^T fp16 [u][k]
__device__ __half g_Ah[(size_t)ROWS*DD];  // passage fp16 (64MB)

// ---------------- helpers ----------------
__device__ __forceinline__ uint32_t smem_u32(const void* p) {
    uint32_t a;
    asm("{ .reg .u64 t; cvta.to.shared.u64 t, %1; cvt.u32.u64 %0, t; }" : "=r"(a) : "l"(p));
    return a;
}
__device__ __forceinline__ void ldsm_x4(uint32_t addr, uint32_t &r0, uint32_t &r1,
                                        uint32_t &r2, uint32_t &r3) {
    asm volatile("ldmatrix.sync.aligned.m8n8.x4.shared.b16 {%0,%1,%2,%3}, [%4];"
        : "=r"(r0), "=r"(r1), "=r"(r2), "=r"(r3) : "r"(addr));
}
__device__ __forceinline__ void mma_fp16(float* d, const uint32_t* a,
                                         uint32_t b0, uint32_t b1) {
    asm volatile("mma.sync.aligned.m16n8k16.row.col.f32.f16.f16.f32 "
        "{%0,%1,%2,%3}, {%4,%5,%6,%7}, {%8,%9}, {%0,%1,%2,%3};"
        : "+f"(d[0]), "+f"(d[1]), "+f"(d[2]), "+f"(d[3])
        : "r"(a[0]), "r"(a[1]), "r"(a[2]), "r"(a[3]), "r"(b0), "r"(b1));
}
__device__ __forceinline__ uint32_t pack_h2(float x, float y) {
    __half2 h = __float22half2_rn(make_float2(x, y));
    return *(uint32_t*)&h;
}
__device__ __forceinline__ void cp16(uint32_t d, const void* s) {
    asm volatile("cp.async.cg.shared.global [%0], [%1], 16;" :: "r"(d), "l"(s));
}
__device__ __forceinline__ void cp_commit() { asm volatile("cp.async.commit_group;" ::: "memory"); }
__device__ __forceinline__ void cp_wait1()  { asm volatile("cp.async.wait_group 1;" ::: "memory"); }
__device__ __forceinline__ void cp_wait0()  { asm volatile("cp.async.wait_group 0;" ::: "memory"); }
__device__ __forceinline__ float fast_tanh(float x) {
    float e = __expf(2.0f * x);
    return 1.0f - __fdividef(2.0f, e + 1.0f);
}

// =====================================================================
// FUSED prep: a2h | hproj | w1half
// =====================================================================
__global__ __launch_bounds__(512)
void prep_kernel(const float* __restrict__ passage,
                 const float* __restrict__ hidden,
                 const float* __restrict__ W2,
                 const float* __restrict__ W1) {
    __shared__ float sh[32][33];
    const int blk = blockIdx.x;
    const int tid = threadIdx.x;

    if (blk < PREP_A2H_BLOCKS) {
        const size_t i = ((size_t)blk * 512 + tid) * 8;
        float4 f0 = *(const float4*)(passage + i);
        float4 f1 = *(const float4*)(passage + i + 4);
        uint4 h = make_uint4(pack_h2(f0.x, f0.y), pack_h2(f0.z, f0.w),
                             pack_h2(f1.x, f1.y), pack_h2(f1.z, f1.w));
        *(uint4*)(g_Ah + i) = h;
    } else if (blk < PREP_A2H_BLOCKS + PREP_HPROJ_BLOCKS) {
        const int b = blk - PREP_A2H_BLOCKS;
        float* h_s = &sh[0][0];
        h_s[tid] = hidden[b*DD + tid];
        __syncthreads();
        float acc = 0.f;
#pragma unroll 8
        for (int d = 0; d < DD; d++)
            acc = fmaf(h_s[d], W2[d*UU + tid], acc);
        g_hp[b*UU + tid] = acc;
    } else {
        const int tile = blk - (PREP_A2H_BLOCKS + PREP_HPROJ_BLOCKS);
        const int bx = tile & 15, by = tile >> 4;
        const int tx = tid & 31, ty0 = tid >> 5;
#pragma unroll
        for (int r = 0; r < 2; r++) {
            const int ty = ty0 + r*16;
            sh[ty][tx] = W1[(by*32 + ty)*UU + bx*32 + tx];
        }
        __syncthreads();
#pragma unroll
        for (int r = 0; r < 2; r++) {
            const int ty = ty0 + r*16;
            g_Bh[(bx*32 + ty)*DD + by*32 + tx] = __float2half(sh[tx][ty]);
        }
    }
}

// =====================================================================
// Score GEMM (exact R8 config — measured best 146.6us)
// =====================================================================
__global__ __launch_bounds__(512, 1)
void score_gemm_tc(const float* __restrict__ Vw) {
    extern __shared__ __align__(16) char dsm[];
    float* hp_s = (float*)(dsm + SM_HP);
    float* vw_s = (float*)(dsm + SM_VW);
    float (*red)[4] = (float(*)[4])(dsm + SM_RED);

    const int nt = blockIdx.x;
    const int mt = blockIdx.y;
    const int n0 = nt * 128;
    const int m0 = mt * 256;
    const int b  = mt >> 3;
    const int tid = threadIdx.x;
    const int wid = tid >> 5;
    const int lid = tid & 31;
    const int warp_m = wid >> 2;
    const int warp_n = wid & 3;

    if (tid < 128) {
        hp_s[tid] = g_hp[b*UU + n0 + tid];
        vw_s[tid] = Vw[n0 + tid];
    }

    const uint32_t uBase = smem_u32(dsm);

    const int arow = tid >> 1;
    const int ahalf = (tid & 1);
    const __half* asrc = g_Ah + (size_t)(m0 + arow) * DD + ahalf * 32;
    const uint32_t adst = (uint32_t)(arow * PITCH + ahalf * 64);
    const int brow = tid >> 2;
    const int bq   = tid & 3;
    const __half* bsrc = g_Bh + (size_t)(n0 + brow) * DD + bq * 16;
    const uint32_t bdst = (uint32_t)(36864 + brow * PITCH + bq * 32);

    const int lm_row = (lid & 7) + ((lid >> 3) & 1) * 8;
    const int lm_kof = (lid >> 4) * 8;
    uint32_t a_lm[4];
#pragma unroll
    for (int mf = 0; mf < 4; mf++)
        a_lm[mf] = (uint32_t)((warp_m*64 + mf*16 + lm_row) * PITCH + lm_kof * 2);
    const uint32_t b_lm0 = (uint32_t)(36864 + (warp_n*32 + lm_row) * PITCH + lm_kof * 2);
    const uint32_t b_lm1 = (uint32_t)(36864 + (warp_n*32 + 16 + lm_row) * PITCH + lm_kof * 2);

    float acc[4][4][4];
#pragma unroll
    for (int i = 0; i < 4; i++)
#pragma unroll
        for (int j = 0; j < 4; j++)
#pragma unroll
            for (int k = 0; k < 4; k++) acc[i][j][k] = 0.f;

#pragma unroll
    for (int c = 0; c < 2; c++) {
        const uint32_t sb = uBase + c * STG_BYTES;
#pragma unroll
        for (int j = 0; j < 4; j++)
            cp16(sb + adst + j*16, asrc + c*64 + j*8);
#pragma unroll
        for (int j = 0; j < 2; j++)
            cp16(sb + bdst + j*16, bsrc + c*64 + j*8);
        cp_commit();
    }

    for (int c = 0; c < 8; c++) {
        const int st = c % 3;
        if (c == 7) cp_wait0(); else cp_wait1();
        __syncthreads();

        if (c + 2 < 8) {
            const uint32_t sb = uBase + ((c + 2) % 3) * STG_BYTES;
#pragma unroll
            for (int j = 0; j < 4; j++)
                cp16(sb + adst + j*16, asrc + (c+2)*64 + j*8);
#pragma unroll
            for (int j = 0; j < 2; j++)
                cp16(sb + bdst + j*16, bsrc + (c+2)*64 + j*8);
            cp_commit();
        }

        const uint32_t sbase = uBase + st * STG_BYTES;
#pragma unroll
        for (int ks = 0; ks < 4; ks++) {
            const uint32_t ko = ks * 32;
            uint32_t ah[4][4];
#pragma unroll
            for (int mf = 0; mf < 4; mf++)
                ldsm_x4(sbase + a_lm[mf] + ko, ah[mf][0], ah[mf][1], ah[mf][2], ah[mf][3]);
            uint32_t bh[4][2];
            {
                uint32_t r0, r1, r2, r3;
                ldsm_x4(sbase + b_lm0 + ko, r0, r1, r2, r3);
                bh[0][0] = r0; bh[0][1] = r2; bh[1][0] = r1; bh[1][1] = r3;
                ldsm_x4(sbase + b_lm1 + ko, r0, r1, r2, r3);
                bh[2][0] = r0; bh[2][1] = r2; bh[3][0] = r1; bh[3][1] = r3;
            }
#pragma unroll
            for (int mf = 0; mf < 4; mf++)
#pragma unroll
                for (int nf = 0; nf < 4; nf++)
                    mma_fp16(acc[mf][nf], ah[mf], bh[nf][0], bh[nf][1]);
        }
    }
    __syncthreads();

#pragma unroll
    for (int mf = 0; mf < 4; mf++) {
        float plo = 0.f, phi = 0.f;
#pragma unroll
        for (int nf = 0; nf < 4; nf++) {
            const int n = warp_n*32 + nf*8 + (lid & 3)*2;
            const float* cc = acc[mf][nf];
            plo = fmaf(fast_tanh(cc[0] + hp_s[n]),   vw_s[n],   plo);
            plo = fmaf(fast_tanh(cc[1] + hp_s[n+1]), vw_s[n+1], plo);
            phi = fmaf(fast_tanh(cc[2] + hp_s[n]),   vw_s[n],   phi);
            phi = fmaf(fast_tanh(cc[3] + hp_s[n+1]), vw_s[n+1], phi);
        }
        plo += __shfl_xor_sync(0xffffffff, plo, 1);
        plo += __shfl_xor_sync(0xffffffff, plo, 2);
        phi += __shfl_xor_sync(0xffffffff, phi, 1);
        phi += __shfl_xor_sync(0xffffffff, phi, 2);
        if ((lid & 3) == 0) {
            const int row = warp_m*64 + mf*16 + (lid >> 2);
            red[row][warp_n]     = plo;
            red[row + 8][warp_n] = phi;
        }
    }
    __syncthreads();
    if (tid < 256)
        g_partial[nt][m0 + tid] = red[tid][0] + red[tid][1] + red[tid][2] + red[tid][3];
}

// =====================================================================
// FUSED softmax + context slice. Grid (16 d-slices, 32 batches), 512 thr.
// Every block recomputes the per-batch softmax (deterministic, identical),
// slice-0 blocks write attention weights; all blocks stream their 32-half
// d-slice of the context sum.
// =====================================================================
__global__ __launch_bounds__(512)
void ctx_softmax_kernel(const float* __restrict__ mask,
                        const float* __restrict__ Vb,
                        float* __restrict__ out) {
    const int slice = blockIdx.x;    // 0..15 (32 halfs each)
    const int b     = blockIdx.y;    // 0..31
    const int tid   = threadIdx.x;   // 512
    const int wid   = tid >> 5;
    const int lid   = tid & 31;
    __shared__ float sc[SS];         // scores -> weights (8KB)
    __shared__ float wred[16];
    __shared__ float bc;
    __shared__ float redc[512][8];   // 16KB

    // ---- softmax (recomputed identically by every block of this batch) ----
    const float vb = Vb[0];
    float lmax = -1e38f;
#pragma unroll
    for (int i = 0; i < 4; i++) {
        const int s = tid + i*512;
        float v = g_partial[0][b*SS + s] + g_partial[1][b*SS + s]
                + g_partial[2][b*SS + s] + g_partial[3][b*SS + s] + vb;
        v += (1.0f - mask[b*SS + s]) * -1e30f;
        sc[s] = v;
        lmax = fmaxf(lmax, v);
    }
#pragma unroll
    for (int o = 16; o > 0; o >>= 1)
        lmax = fmaxf(lmax, __shfl_xor_sync(0xffffffff, lmax, o));
    if (lid == 0) wred[wid] = lmax;
    __syncthreads();
    if (wid == 0) {
        float m = (lid < 16) ? wred[lid] : -1e38f;
#pragma unroll
        for (int o = 8; o > 0; o >>= 1)
            m = fmaxf(m, __shfl_xor_sync(0xffffffff, m, o));
        if (lid == 0) bc = m;
    }
    __syncthreads();
    const float m = bc;

    float lsum = 0.f;
#pragma unroll
    for (int i = 0; i < 4; i++) {
        const int s = tid + i*512;
        float e = expf(sc[s] - m);
        sc[s] = e;
        lsum += e;
    }
#pragma unroll
    for (int o = 16; o > 0; o >>= 1)
        lsum += __shfl_xor_sync(0xffffffff, lsum, o);
    if (lid == 0) wred[wid] = lsum;
    __syncthreads();
    if (wid == 0) {
        float sm = (lid < 16) ? wred[lid] : 0.f;
#pragma unroll
        for (int o = 8; o > 0; o >>= 1)
            sm += __shfl_xor_sync(0xffffffff, sm, o);
        if (lid == 0) bc = sm;
    }
    __syncthreads();
    const float inv = 1.0f / bc;
#pragma unroll
    for (int i = 0; i < 4; i++) {
        const int s = tid + i*512;
        const float w = sc[s] * inv;
        sc[s] = w;
        if (slice == 0) out[BB*DD + b*SS + s] = w;
    }
    __syncthreads();

    // ---- context slice: 32 halfs, 4 uint4-groups x 128 s-groups ----
    const int dq   = tid & 3;        // 0..3 (8 halfs each)
    const int sgrp = tid >> 2;       // 0..127
    float acc[8];
#pragma unroll
    for (int j = 0; j < 8; j++) acc[j] = 0.f;

    const __half* base = g_Ah + (size_t)b*SS*DD + slice*32 + dq*8;
#pragma unroll 4
    for (int s = sgrp; s < SS; s += 128) {
        uint4 v = *(const uint4*)(base + (size_t)s * DD);
        const float w = sc[s];
        const __half2* h = (const __half2*)&v;
#pragma unroll
        for (int j = 0; j < 4; j++) {
            float2 f = __half22float2(h[j]);
            acc[2*j]   = fmaf(w, f.x, acc[2*j]);
            acc[2*j+1] = fmaf(w, f.y, acc[2*j+1]);
        }
    }
#pragma unroll
    for (int j = 0; j < 8; j++) redc[tid][j] = acc[j];
    __syncthreads();

    // final reduce: thread t (<32) owns d = slice*32 + t
    if (tid < 32) {
        const int tdq = tid >> 3;
        const int tj  = tid & 7;
        float r = 0.f;
#pragma unroll 8
        for (int g = 0; g < 128; g++)
            r += redc[g*4 + tdq][tj];
        out[b*DD + slice*32 + tid] = r;
    }
}

// =====================================================================
extern "C" void kernel_launch(void* const* d_in, const int* in_sizes, int n_in,
                              void* d_out, int out_size) {
    const float* passage = (const float*)d_in[0];
    const float* hidden  = (const float*)d_in[1];
    const float* mask    = (const float*)d_in[2];
    const float* W1      = (const float*)d_in[3];
    const float* W2      = (const float*)d_in[4];
    const float* Vw      = (const float*)d_in[5];
    const float* Vb      = (const float*)d_in[6];
    float* out = (float*)d_out;

    cudaFuncSetAttribute(score_gemm_tc, cudaFuncAttributeMaxDynamicSharedMemorySize, SM_SCORE_BYTES);

    prep_kernel<<<PREP_BLOCKS, 512>>>(passage, hidden, W2, W1);
    score_gemm_tc<<<dim3(NTILES, 256), 512, SM_SCORE_BYTES>>>(Vw);
    ctx_softmax_kernel<<<dim3(16, BB), 512>>>(mask, Vb, out);
}

// round 15
// speedup vs baseline: 1.0156x; 1.0156x over previous
#include <cuda_runtime.h>
#include <cuda_fp16.h>
#include <cstdint>

#define BB 32
#define SS 2048
#define DD 512
#define UU 512
#define ROWS (BB*SS)          // 65536
#define NTILES 4
#define PITCH 144             // 64 halfs (128B) + 16B pad; conflict-free ldsm

// dynamic smem: 3 stages of (A 256x144 | B 128x144)  [R8 config — measured best]
#define STG_BYTES 55296
#define SM_HP  165888
#define SM_VW  166400
#define SM_RED 166912
#define SM_SCORE_BYTES 171008

// prep kernel dispatch (a2h: 32 floats/thread -> 2048 blocks)
#define PREP_A2H_BLOCKS   2048
#define PREP_HPROJ_BLOCKS 32
#define PREP_W1_BLOCKS    256
#define PREP_BLOCKS (PREP_A2H_BLOCKS + PREP_HPROJ_BLOCKS + PREP_W1_BLOCKS)

// ---------------- scratch (no allocation allowed) ----------------
__device__ float g_hp[BB*UU];
__device__ float g_partial[NTILES][ROWS];
__device__ __half g_Bh[UU*DD];            // W1^T fp16 [u][k]
__device__ __half g_Ah[(size_t)ROWS*DD];  // passage fp16 (64MB)

// ---------------- helpers ----------------
__device__ __forceinline__ uint32_t smem_u32(const void* p) {
    uint32_t a;
    asm("{ .reg .u64 t; cvta.to.shared.u64 t, %1; cvt.u32.u64 %0, t; }" : "=r"(a) : "l"(p));
    return a;
}
__device__ __forceinline__ void ldsm_x4(uint32_t addr, uint32_t &r0, uint32_t &r1,
                                        uint32_t &r2, uint32_t &r3) {
    asm volatile("ldmatrix.sync.aligned.m8n8.x4.shared.b16 {%0,%1,%2,%3}, [%4];"
        : "=r"(r0), "=r"(r1), "=r"(r2), "=r"(r3) : "r"(addr));
}
__device__ __forceinline__ void mma_fp16(float* d, const uint32_t* a,
                                         uint32_t b0, uint32_t b1) {
    asm volatile("mma.sync.aligned.m16n8k16.row.col.f32.f16.f16.f32 "
        "{%0,%1,%2,%3}, {%4,%5,%6,%7}, {%8,%9}, {%0,%1,%2,%3};"
        : "+f"(d[0]), "+f"(d[1]), "+f"(d[2]), "+f"(d[3])
        : "r"(a[0]), "r"(a[1]), "r"(a[2]), "r"(a[3]), "r"(b0), "r"(b1));
}
__device__ __forceinline__ uint32_t pack_h2(float x, float y) {
    __half2 h = __float22half2_rn(make_float2(x, y));
    return *(uint32_t*)&h;
}
__device__ __forceinline__ void cp16(uint32_t d, const void* s) {
    asm volatile("cp.async.cg.shared.global [%0], [%1], 16;" :: "r"(d), "l"(s));
}
__device__ __forceinline__ void cp_commit() { asm volatile("cp.async.commit_group;" ::: "memory"); }
__device__ __forceinline__ void cp_wait1()  { asm volatile("cp.async.wait_group 1;" ::: "memory"); }
__device__ __forceinline__ void cp_wait0()  { asm volatile("cp.async.wait_group 0;" ::: "memory"); }
__device__ __forceinline__ float fast_tanh(float x) {
    float e = __expf(2.0f * x);
    return 1.0f - __fdividef(2.0f, e + 1.0f);
}

// =====================================================================
// FUSED prep: a2h (MLP=8) | hproj | w1half
// =====================================================================
__global__ __launch_bounds__(512)
void prep_kernel(const float* __restrict__ passage,
                 const float* __restrict__ hidden,
                 const float* __restrict__ W2,
                 const float* __restrict__ W1) {
    __shared__ float sh[32][33];
    const int blk = blockIdx.x;
    const int tid = threadIdx.x;

    if (blk < PREP_A2H_BLOCKS) {
        // ---- passage fp32 -> fp16, 32 floats/thread, 8 loads in flight ----
        const size_t base = (size_t)blk * (512*32);
        float4 f[8];
#pragma unroll
        for (int j = 0; j < 4; j++) {
            const size_t off = base + (size_t)j*(512*8) + (size_t)tid*8;
            f[2*j]   = *(const float4*)(passage + off);
            f[2*j+1] = *(const float4*)(passage + off + 4);
        }
#pragma unroll
        for (int j = 0; j < 4; j++) {
            const size_t off = base + (size_t)j*(512*8) + (size_t)tid*8;
            uint4 h = make_uint4(pack_h2(f[2*j].x,   f[2*j].y),
                                 pack_h2(f[2*j].z,   f[2*j].w),
                                 pack_h2(f[2*j+1].x, f[2*j+1].y),
                                 pack_h2(f[2*j+1].z, f[2*j+1].w));
            *(uint4*)(g_Ah + off) = h;
        }
    } else if (blk < PREP_A2H_BLOCKS + PREP_HPROJ_BLOCKS) {
        const int b = blk - PREP_A2H_BLOCKS;
        float* h_s = &sh[0][0];
        h_s[tid] = hidden[b*DD + tid];
        __syncthreads();
        float acc = 0.f;
#pragma unroll 8
        for (int d = 0; d < DD; d++)
            acc = fmaf(h_s[d], W2[d*UU + tid], acc);
        g_hp[b*UU + tid] = acc;
    } else {
        const int tile = blk - (PREP_A2H_BLOCKS + PREP_HPROJ_BLOCKS);
        const int bx = tile & 15, by = tile >> 4;
        const int tx = tid & 31, ty0 = tid >> 5;
#pragma unroll
        for (int r = 0; r < 2; r++) {
            const int ty = ty0 + r*16;
            sh[ty][tx] = W1[(by*32 + ty)*UU + bx*32 + tx];
        }
        __syncthreads();
#pragma unroll
        for (int r = 0; r < 2; r++) {
            const int ty = ty0 + r*16;
            g_Bh[(bx*32 + ty)*DD + by*32 + tx] = __float2half(sh[tx][ty]);
        }
    }
}

// =====================================================================
// Score GEMM (exact R8 config — measured best 146.6us)
// =====================================================================
__global__ __launch_bounds__(512, 1)
void score_gemm_tc(const float* __restrict__ Vw) {
    extern __shared__ __align__(16) char dsm[];
    float* hp_s = (float*)(dsm + SM_HP);
    float* vw_s = (float*)(dsm + SM_VW);
    float (*red)[4] = (float(*)[4])(dsm + SM_RED);

    const int nt = blockIdx.x;
    const int mt = blockIdx.y;
    const int n0 = nt * 128;
    const int m0 = mt * 256;
    const int b  = mt >> 3;
    const int tid = threadIdx.x;
    const int wid = tid >> 5;
    const int lid = tid & 31;
    const int warp_m = wid >> 2;
    const int warp_n = wid & 3;

    if (tid < 128) {
        hp_s[tid] = g_hp[b*UU + n0 + tid];
        vw_s[tid] = Vw[n0 + tid];
    }

    const uint32_t uBase = smem_u32(dsm);

    const int arow = tid >> 1;
    const int ahalf = (tid & 1);
    const __half* asrc = g_Ah + (size_t)(m0 + arow) * DD + ahalf * 32;
    const uint32_t adst = (uint32_t)(arow * PITCH + ahalf * 64);
    const int brow = tid >> 2;
    const int bq   = tid & 3;
    const __half* bsrc = g_Bh + (size_t)(n0 + brow) * DD + bq * 16;
    const uint32_t bdst = (uint32_t)(36864 + brow * PITCH + bq * 32);

    const int lm_row = (lid & 7) + ((lid >> 3) & 1) * 8;
    const int lm_kof = (lid >> 4) * 8;
    uint32_t a_lm[4];
#pragma unroll
    for (int mf = 0; mf < 4; mf++)
        a_lm[mf] = (uint32_t)((warp_m*64 + mf*16 + lm_row) * PITCH + lm_kof * 2);
    const uint32_t b_lm0 = (uint32_t)(36864 + (warp_n*32 + lm_row) * PITCH + lm_kof * 2);
    const uint32_t b_lm1 = (uint32_t)(36864 + (warp_n*32 + 16 + lm_row) * PITCH + lm_kof * 2);

    float acc[4][4][4];
#pragma unroll
    for (int i = 0; i < 4; i++)
#pragma unroll
        for (int j = 0; j < 4; j++)
#pragma unroll
            for (int k = 0; k < 4; k++) acc[i][j][k] = 0.f;

#pragma unroll
    for (int c = 0; c < 2; c++) {
        const uint32_t sb = uBase + c * STG_BYTES;
#pragma unroll
        for (int j = 0; j < 4; j++)
            cp16(sb + adst + j*16, asrc + c*64 + j*8);
#pragma unroll
        for (int j = 0; j < 2; j++)
            cp16(sb + bdst + j*16, bsrc + c*64 + j*8);
        cp_commit();
    }

    for (int c = 0; c < 8; c++) {
        const int st = c % 3;
        if (c == 7) cp_wait0(); else cp_wait1();
        __syncthreads();

        if (c + 2 < 8) {
            const uint32_t sb = uBase + ((c + 2) % 3) * STG_BYTES;
#pragma unroll
            for (int j = 0; j < 4; j++)
                cp16(sb + adst + j*16, asrc + (c+2)*64 + j*8);
#pragma unroll
            for (int j = 0; j < 2; j++)
                cp16(sb + bdst + j*16, bsrc + (c+2)*64 + j*8);
            cp_commit();
        }

        const uint32_t sbase = uBase + st * STG_BYTES;
#pragma unroll
        for (int ks = 0; ks < 4; ks++) {
            const uint32_t ko = ks * 32;
            uint32_t ah[4][4];
#pragma unroll
            for (int mf = 0; mf < 4; mf++)
                ldsm_x4(sbase + a_lm[mf] + ko, ah[mf][0], ah[mf][1], ah[mf][2], ah[mf][3]);
            uint32_t bh[4][2];
            {
                uint32_t r0, r1, r2, r3;
                ldsm_x4(sbase + b_lm0 + ko, r0, r1, r2, r3);
                bh[0][0] = r0; bh[0][1] = r2; bh[1][0] = r1; bh[1][1] = r3;
                ldsm_x4(sbase + b_lm1 + ko, r0, r1, r2, r3);
                bh[2][0] = r0; bh[2][1] = r2; bh[3][0] = r1; bh[3][1] = r3;
            }
#pragma unroll
            for (int mf = 0; mf < 4; mf++)
#pragma unroll
                for (int nf = 0; nf < 4; nf++)
                    mma_fp16(acc[mf][nf], ah[mf], bh[nf][0], bh[nf][1]);
        }
    }
    __syncthreads();

#pragma unroll
    for (int mf = 0; mf < 4; mf++) {
        float plo = 0.f, phi = 0.f;
#pragma unroll
        for (int nf = 0; nf < 4; nf++) {
            const int n = warp_n*32 + nf*8 + (lid & 3)*2;
            const float* cc = acc[mf][nf];
            plo = fmaf(fast_tanh(cc[0] + hp_s[n]),   vw_s[n],   plo);
            plo = fmaf(fast_tanh(cc[1] + hp_s[n+1]), vw_s[n+1], plo);
            phi = fmaf(fast_tanh(cc[2] + hp_s[n]),   vw_s[n],   phi);
            phi = fmaf(fast_tanh(cc[3] + hp_s[n+1]), vw_s[n+1], phi);
        }
        plo += __shfl_xor_sync(0xffffffff, plo, 1);
        plo += __shfl_xor_sync(0xffffffff, plo, 2);
        phi += __shfl_xor_sync(0xffffffff, phi, 1);
        phi += __shfl_xor_sync(0xffffffff, phi, 2);
        if ((lid & 3) == 0) {
            const int row = warp_m*64 + mf*16 + (lid >> 2);
            red[row][warp_n]     = plo;
            red[row + 8][warp_n] = phi;
        }
    }
    __syncthreads();
    if (tid < 256)
        g_partial[nt][m0 + tid] = red[tid][0] + red[tid][1] + red[tid][2] + red[tid][3];
}

// =====================================================================
// softmax over S per batch — shuffle reductions (512 threads)
// =====================================================================
__global__ __launch_bounds__(512)
void softmax_kernel(const float* __restrict__ mask,
                    const float* __restrict__ Vb,
                    float* __restrict__ out) {
    const int b   = blockIdx.x;
    const int tid = threadIdx.x;
    const int wid = tid >> 5;
    const int lid = tid & 31;
    __shared__ float sc[SS];
    __shared__ float wred[16];
    __shared__ float bc;

    const float vb = Vb[0];
    float lmax = -1e38f;
#pragma unroll
    for (int i = 0; i < 4; i++) {
        const int s = tid + i*512;
        float v = g_partial[0][b*SS + s] + g_partial[1][b*SS + s]
                + g_partial[2][b*SS + s] + g_partial[3][b*SS + s] + vb;
        v += (1.0f - mask[b*SS + s]) * -1e30f;
        sc[s] = v;
        lmax = fmaxf(lmax, v);
    }
#pragma unroll
    for (int o = 16; o > 0; o >>= 1)
        lmax = fmaxf(lmax, __shfl_xor_sync(0xffffffff, lmax, o));
    if (lid == 0) wred[wid] = lmax;
    __syncthreads();
    if (wid == 0) {
        float m = (lid < 16) ? wred[lid] : -1e38f;
#pragma unroll
        for (int o = 8; o > 0; o >>= 1)
            m = fmaxf(m, __shfl_xor_sync(0xffffffff, m, o));
        if (lid == 0) bc = m;
    }
    __syncthreads();
    const float m = bc;

    float lsum = 0.f;
#pragma unroll
    for (int i = 0; i < 4; i++) {
        const int s = tid + i*512;
        float e = expf(sc[s] - m);
        sc[s] = e;
        lsum += e;
    }
#pragma unroll
    for (int o = 16; o > 0; o >>= 1)
        lsum += __shfl_xor_sync(0xffffffff, lsum, o);
    if (lid == 0) wred[wid] = lsum;
    __syncthreads();
    if (wid == 0) {
        float sm = (lid < 16) ? wred[lid] : 0.f;
#pragma unroll
        for (int o = 8; o > 0; o >>= 1)
            sm += __shfl_xor_sync(0xffffffff, sm, o);
        if (lid == 0) bc = sm;
    }
    __syncthreads();
    const float inv = 1.0f / bc;
#pragma unroll
    for (int i = 0; i < 4; i++) {
        const int s = tid + i*512;
        out[BB*DD + b*SS + s] = sc[s] * inv;
    }
}

// =====================================================================
// Single-pass context: grid (16 d-slices, 32 batches), 512 threads.
// 32-half slices for higher occupancy.
// =====================================================================
__global__ __launch_bounds__(512)
void ctx_kernel(const float* __restrict__ out_r, float* __restrict__ out) {
    const int slice = blockIdx.x;    // 0..15 (32 halfs each)
    const int b     = blockIdx.y;    // 0..31
    const int tid   = threadIdx.x;   // 512
    const int dq    = tid & 3;       // 0..3 (uint4 = 8 halfs)
    const int sgrp  = tid >> 2;      // 0..127
    __shared__ float w_s[SS];
    __shared__ float redc[512][8];

#pragma unroll
    for (int i = 0; i < 4; i++)
        w_s[tid + i*512] = out_r[BB*DD + b*SS + tid + i*512];
    __syncthreads();

    float acc[8];
#pragma unroll
    for (int j = 0; j < 8; j++) acc[j] = 0.f;

    const __half* base = g_Ah + (size_t)b*SS*DD + slice*32 + dq*8;
#pragma unroll 4
    for (int s = sgrp; s < SS; s += 128) {
        uint4 v = *(const uint4*)(base + (size_t)s * DD);
        const float w = w_s[s];
        const __half2* h = (const __half2*)&v;
#pragma unroll
        for (int j = 0; j < 4; j++) {
            float2 f = __half22float2(h[j]);
            acc[2*j]   = fmaf(w, f.x, acc[2*j]);
            acc[2*j+1] = fmaf(w, f.y, acc[2*j+1]);
        }
    }
#pragma unroll
    for (int j = 0; j < 8; j++) redc[tid][j] = acc[j];
    __syncthreads();

    if (tid < 32) {
        const int tdq = tid >> 3;
        const int tj  = tid & 7;
        float r = 0.f;
#pragma unroll 8
        for (int g = 0; g < 128; g++)
            r += redc[g*4 + tdq][tj];
        out[b*DD + slice*32 + tid] = r;
    }
}

// =====================================================================
extern "C" void kernel_launch(void* const* d_in, const int* in_sizes, int n_in,
                              void* d_out, int out_size) {
    const float* passage = (const float*)d_in[0];
    const float* hidden  = (const float*)d_in[1];
    const float* mask    = (const float*)d_in[2];
    const float* W1      = (const float*)d_in[3];
    const float* W2      = (const float*)d_in[4];
    const float* Vw      = (const float*)d_in[5];
    const float* Vb      = (const float*)d_in[6];
    float* out = (float*)d_out;

    cudaFuncSetAttribute(score_gemm_tc, cudaFuncAttributeMaxDynamicSharedMemorySize, SM_SCORE_BYTES);

    prep_kernel<<<PREP_BLOCKS, 512>>>(passage, hidden, W2, W1);
    score_gemm_tc<<<dim3(NTILES, 256), 512, SM_SCORE_BYTES>>>(Vw);
    softmax_kernel<<<BB, 512>>>(mask, Vb, out);
    ctx_kernel<<<dim3(16, BB), 512>>>(out, out);
}